// round 15
// baseline (speedup 1.0000x reference)
#include <cuda_runtime.h>
#include <cuda_fp16.h>
#include <cstdint>
#include <math.h>

#define N_TOK 8192
#define DIM   1024
#define HDIM  4096
#define NEXP  8
#define NSLOT 16384
#define CAP   17408            // 16384 + 8*128 pad (per-expert pad to 128)
#define MAXTILES 136           // CAP / 128
#define BN    256              // CTA cols
#define KSTG  64               // K halves per stage (128B rows)
#define STAGE_BYTES ((128 + BN) * 128)   // A 16KB + B 32KB = 49152
#define NSTAGE 4
#define NTHR  512

// ---------------- scratch (static __device__: no runtime alloc) ------------
__device__ __half g_Hh [(size_t)CAP   * HDIM];       // 142 MB relu^2 out, fp16
__device__ __half g_xh  [(size_t)N_TOK * DIM];       // 16 MB  x in fp16
__device__ __half g_wfch[(size_t)NEXP * HDIM * DIM]; // 64 MB w_fc fp16
__device__ __half g_wpjh[(size_t)NEXP * HDIM * DIM]; // 64 MB w_proj fp16
__device__ int   g_rowTok[CAP];
__device__ float g_rowW[CAP];
__device__ int   g_slotE[NSLOT];
__device__ float g_slotW[NSLOT];
__device__ int   g_cnt[NEXP];
__device__ int   g_cursor[NEXP];
__device__ int   g_padOff[NEXP + 1];
__device__ int   g_tileE[MAXTILES];
__device__ float g_probSum[NEXP];

// ---------------- helpers ---------------------------------------------------
__device__ __forceinline__ uint32_t smem_to_u32(const void* p) {
    uint32_t a;
    asm("{ .reg .u64 t; cvta.to.shared.u64 t, %1; cvt.u32.u64 %0, t; }"
        : "=r"(a) : "l"(p));
    return a;
}
__device__ __forceinline__ void cpasync16(uint32_t s, const void* g) {
    asm volatile("cp.async.cg.shared.global [%0], [%1], 16;" :: "r"(s), "l"(g) : "memory");
}
__device__ __forceinline__ void ldsm4(uint32_t& r0, uint32_t& r1, uint32_t& r2,
                                      uint32_t& r3, uint32_t addr) {
    asm volatile("ldmatrix.sync.aligned.m8n8.x4.shared.b16 {%0,%1,%2,%3}, [%4];"
                 : "=r"(r0), "=r"(r1), "=r"(r2), "=r"(r3) : "r"(addr));
}
__device__ __forceinline__ void mma_f16(float* c, const uint32_t* a,
                                        uint32_t b0, uint32_t b1) {
    asm volatile(
        "mma.sync.aligned.m16n8k16.row.col.f32.f16.f16.f32 "
        "{%0,%1,%2,%3}, {%4,%5,%6,%7}, {%8,%9}, {%0,%1,%2,%3};"
        : "+f"(c[0]), "+f"(c[1]), "+f"(c[2]), "+f"(c[3])
        : "r"(a[0]), "r"(a[1]), "r"(a[2]), "r"(a[3]), "r"(b0), "r"(b1));
}

// ---------------- K_half: fp32 -> fp16 bulk convert (weights) ---------------
__global__ void k_half(const float4* __restrict__ in, uint2* __restrict__ out, int n4) {
    int i = blockIdx.x * blockDim.x + threadIdx.x;
    if (i >= n4) return;
    float4 v = in[i];
    __half2 h0 = __floats2half2_rn(v.x, v.y);
    __half2 h1 = __floats2half2_rn(v.z, v.w);
    out[i] = make_uint2(*(uint32_t*)&h0, *(uint32_t*)&h1);
}

// ---------------- K_zero: clear token part of out ---------------------------
__global__ void k_zero(float4* __restrict__ out) {
    int i = blockIdx.x * blockDim.x + threadIdx.x;
    if (i < N_TOK * (DIM / 4)) out[i] = make_float4(0.f, 0.f, 0.f, 0.f);
}

// ---------------- K0: reset -------------------------------------------------
__global__ void k_init() {
    int i = blockIdx.x * blockDim.x + threadIdx.x;
    if (i < CAP) g_rowTok[i] = -1;
    if (i < NEXP) { g_cnt[i] = 0; g_cursor[i] = 0; g_probSum[i] = 0.f; }
}

// ---------------- K1: gating (exact fp32) + x -> fp16 write -----------------
__global__ __launch_bounds__(256) void k_gate(const float* __restrict__ x,
                                              const float* __restrict__ gw) {
    __shared__ float sProb[NEXP];
    __shared__ int   sCnt[NEXP];
    int tid = threadIdx.x;
    if (tid < NEXP) { sProb[tid] = 0.f; sCnt[tid] = 0; }
    __syncthreads();
    int warp = tid >> 5, lane = tid & 31;
    int n = blockIdx.x * 8 + warp;
    const float* xr = x + (size_t)n * DIM;
    float xv[32];
    #pragma unroll
    for (int j = 0; j < 32; j++) xv[j] = xr[j * 32 + lane];

    // fused fp16 conversion of x
    __half* xo = g_xh + (size_t)n * DIM;
    #pragma unroll
    for (int j = 0; j < 32; j++) xo[j * 32 + lane] = __float2half_rn(xv[j]);

    float logit[NEXP];
    #pragma unroll
    for (int e = 0; e < NEXP; e++) {
        const float* g = gw + e * DIM;
        float s = 0.f;
        #pragma unroll
        for (int j = 0; j < 32; j++) s += xv[j] * g[j * 32 + lane];
        #pragma unroll
        for (int o = 16; o; o >>= 1) s += __shfl_xor_sync(0xffffffffu, s, o);
        logit[e] = s;
    }
    if (lane == 0) {
        float m = logit[0];
        #pragma unroll
        for (int e = 1; e < NEXP; e++) m = fmaxf(m, logit[e]);
        float p[NEXP]; float Z = 0.f;
        #pragma unroll
        for (int e = 0; e < NEXP; e++) { p[e] = expf(logit[e] - m); Z += p[e]; }
        float inv = 1.f / Z;
        #pragma unroll
        for (int e = 0; e < NEXP; e++) p[e] *= inv;
        int i1 = 0;
        #pragma unroll
        for (int e = 1; e < NEXP; e++) if (p[e] > p[i1]) i1 = e;
        int i2 = (i1 == 0) ? 1 : 0;
        #pragma unroll
        for (int e = 0; e < NEXP; e++) if (e != i1 && p[e] > p[i2]) i2 = e;
        float s2 = p[i1] + p[i2];
        g_slotE[2 * n]     = i1;  g_slotW[2 * n]     = p[i1] / s2;
        g_slotE[2 * n + 1] = i2;  g_slotW[2 * n + 1] = p[i2] / s2;
        atomicAdd(&sCnt[i1], 1);
        atomicAdd(&sCnt[i2], 1);
        #pragma unroll
        for (int e = 0; e < NEXP; e++) atomicAdd(&sProb[e], p[e]);
    }
    __syncthreads();
    if (tid < NEXP) {
        atomicAdd(&g_probSum[tid], sProb[tid]);
        atomicAdd(&g_cnt[tid], sCnt[tid]);
    }
}

// ---------------- K2: scan + tile map + balance loss ------------------------
__global__ void k_scan(float* out, int out_size) {
    if (threadIdx.x != 0 || blockIdx.x != 0) return;
    int off = 0;
    for (int e = 0; e < NEXP; e++) {
        g_padOff[e] = off;
        off += ((g_cnt[e] + 127) >> 7) << 7;
    }
    g_padOff[NEXP] = off;
    for (int e = 0; e < NEXP; e++)
        for (int t = g_padOff[e] >> 7; t < (g_padOff[e + 1] >> 7); t++) g_tileE[t] = e;
    for (int t = off >> 7; t < MAXTILES; t++) g_tileE[t] = -1;
    if (out_size > N_TOK * DIM) {
        float l = 0.f;
        for (int e = 0; e < NEXP; e++) l += g_probSum[e] * (float)g_cnt[e];
        out[(size_t)N_TOK * DIM] = l * (float)NEXP / ((float)N_TOK * (float)N_TOK);
    }
}

// ---------------- K3: scatter -----------------------------------------------
__global__ void k_scatter() {
    int s = blockIdx.x * blockDim.x + threadIdx.x;
    if (s >= NSLOT) return;
    int e = g_slotE[s];
    int pos = g_padOff[e] + atomicAdd(&g_cursor[e], 1);
    g_rowTok[pos] = s >> 1;
    g_rowW[pos]   = g_slotW[s];
}

// ---------------------------------------------------------------------------
// fp16 mma.sync m16n8k16 GEMM. CTA 128x256, 512 threads (4x4 warps of 32x64),
// K-stage 64 halves (128B rows, 8 chunks), 4-stage cp.async pipeline.
// Swizzle: phys_chunk = chunk ^ (row & 7)  (conflict-free writers + ldsm).
// B fragments loaded per-p and consumed immediately: low register pressure.
// MODE 0: A = g_xh rows gathered via g_rowTok, W = g_wfch[e], epi relu^2 -> g_Hh
// MODE 1: A = g_Hh rows (direct), W = g_wpjh[e], epi atomicAdd(w * y) -> outp
// ---------------------------------------------------------------------------
template<int KD, int MODE>
__global__ void __launch_bounds__(NTHR, 1) k_mma(const __half* __restrict__ Ag,
                                                 const __half* __restrict__ Wg,
                                                 float* __restrict__ outp) {
    int e = g_tileE[blockIdx.y];
    if (e < 0) return;
    extern __shared__ char smem[];   // NSTAGE * STAGE_BYTES
    const int tid = threadIdx.x;
    const int rowBase = blockIdx.y << 7;
    const int colBase = blockIdx.x * BN;

    // ---- loader mapping:
    //   A: thread t -> row t>>2, chunks (t&3)*2 .. +1   (2 x cp.async)
    //   B: thread t -> row t>>1, chunks (t&1)*4 .. +3   (4 x cp.async)
    const __half* aSrc;
    {
        int ar = rowBase + (tid >> 2);
        if (MODE == 0) {
            int tok = g_rowTok[ar];
            if (tok < 0) tok = 0;                   // pad rows: valid dummy data
            aSrc = Ag + (size_t)tok * KD;
        } else {
            aSrc = g_Hh + (size_t)ar * KD;
        }
    }
    const __half* bSrc = Wg + (size_t)e * ((size_t)HDIM * DIM)
                       + (size_t)(colBase + (tid >> 1)) * KD;

    const uint32_t sb = smem_to_u32(smem);
    const int acb = (tid & 3) * 2;                  // A chunk base
    const int bcb = (tid & 1) * 4;                  // B chunk base
    uint32_t aOff[2], bOff[4];
    #pragma unroll
    for (int j = 0; j < 2; j++)
        aOff[j] = (tid >> 2) * 128 + (((acb + j) ^ ((tid >> 2) & 7)) << 4);
    #pragma unroll
    for (int j = 0; j < 4; j++)
        bOff[j] = 16384 + (tid >> 1) * 128 + (((bcb + j) ^ ((tid >> 1) & 7)) << 4);

    const int T = KD / KSTG;

    // prologue: stages 0..NSTAGE-2
    #pragma unroll
    for (int t = 0; t < NSTAGE - 1; t++) {
        uint32_t so = sb + t * STAGE_BYTES;
        const __half* ga = aSrc + t * KSTG;
        const __half* gb = bSrc + t * KSTG;
        #pragma unroll
        for (int j = 0; j < 2; j++) cpasync16(so + aOff[j], ga + (acb + j) * 8);
        #pragma unroll
        for (int j = 0; j < 4; j++) cpasync16(so + bOff[j], gb + (bcb + j) * 8);
        asm volatile("cp.async.commit_group;" ::: "memory");
    }

    // ---- compute mapping (ldmatrix lane geometry)
    const int wid = tid >> 5, lane = tid & 31;
    const int wm = wid >> 2, wn = wid & 3;          // 4x4 warps of 32x64
    const int mat = lane >> 3;
    const int l8  = ((mat & 1) << 3) + (lane & 7);  // row-within-16
    const int cm  = mat >> 1;                       // 16B chunk sub-index
    const int rsw = l8 & 7;                         // reader swizzle
    uint32_t pc[4];
    #pragma unroll
    for (int kb = 0; kb < 4; kb++) pc[kb] = (uint32_t)(((2 * kb + cm) ^ rsw) << 4);
    const uint32_t aLane = (uint32_t)(wm * 4096 + l8 * 128);
    const uint32_t bLane = (uint32_t)(16384 + wn * 8192 + l8 * 128);

    float acc[2][8][4];
    #pragma unroll
    for (int i = 0; i < 2; i++)
        #pragma unroll
        for (int j = 0; j < 8; j++)
            #pragma unroll
            for (int q = 0; q < 4; q++) acc[i][j][q] = 0.f;

    for (int jt = 0; jt < T; jt++) {
        if (jt < T - 2)       asm volatile("cp.async.wait_group 2;" ::: "memory");
        else if (jt == T - 2) asm volatile("cp.async.wait_group 1;" ::: "memory");
        else                  asm volatile("cp.async.wait_group 0;" ::: "memory");
        __syncthreads();

        if (jt + NSTAGE - 1 < T) {
            int t = jt + NSTAGE - 1;
            uint32_t so = sb + (t & (NSTAGE - 1)) * STAGE_BYTES;
            const __half* ga = aSrc + t * KSTG;
            const __half* gb = bSrc + t * KSTG;
            #pragma unroll
            for (int j = 0; j < 2; j++) cpasync16(so + aOff[j], ga + (acb + j) * 8);
            #pragma unroll
            for (int j = 0; j < 4; j++) cpasync16(so + bOff[j], gb + (bcb + j) * 8);
            asm volatile("cp.async.commit_group;" ::: "memory");
        }

        const uint32_t so = sb + (jt & (NSTAGE - 1)) * STAGE_BYTES;
        const uint32_t sA = so + aLane;
        const uint32_t sB = so + bLane;

        #pragma unroll
        for (int kb = 0; kb < 4; kb++) {
            const uint32_t c = pc[kb];
            uint32_t a[2][4];
            #pragma unroll
            for (int mt = 0; mt < 2; mt++)
                ldsm4(a[mt][0], a[mt][1], a[mt][2], a[mt][3], sA + mt * 2048 + c);
            #pragma unroll
            for (int p = 0; p < 4; p++) {
                uint32_t b0, b1, b2, b3;
                ldsm4(b0, b1, b2, b3, sB + p * 2048 + c);
                #pragma unroll
                for (int mt = 0; mt < 2; mt++) {
                    mma_f16(acc[mt][2 * p],     a[mt], b0, b2);
                    mma_f16(acc[mt][2 * p + 1], a[mt], b1, b3);
                }
            }
        }
    }

    // ---- epilogue. Frag: c0,c1 -> row qr cols 2qc,2qc+1; c2,c3 -> row qr+8
    const int qr = lane >> 2, qc = lane & 3;
    #pragma unroll
    for (int mt = 0; mt < 2; mt++) {
        const int r0 = rowBase + wm * 32 + mt * 16 + qr;
        const int r1 = r0 + 8;
        if (MODE == 0) {
            #pragma unroll
            for (int nt = 0; nt < 8; nt++) {
                const int cg = colBase + wn * 64 + nt * 8 + 2 * qc;
                float t0 = fmaxf(acc[mt][nt][0], 0.f);
                float t1 = fmaxf(acc[mt][nt][1], 0.f);
                float t2 = fmaxf(acc[mt][nt][2], 0.f);
                float t3 = fmaxf(acc[mt][nt][3], 0.f);
                *(__half2*)(g_Hh + (size_t)r0 * HDIM + cg) = __floats2half2_rn(t0 * t0, t1 * t1);
                *(__half2*)(g_Hh + (size_t)r1 * HDIM + cg) = __floats2half2_rn(t2 * t2, t3 * t3);
            }
        } else {
            int   tok0 = g_rowTok[r0],  tok1 = g_rowTok[r1];
            float w0   = g_rowW[r0],    w1   = g_rowW[r1];
            float* d0 = outp + (size_t)(tok0 < 0 ? 0 : tok0) * DIM;
            float* d1 = outp + (size_t)(tok1 < 0 ? 0 : tok1) * DIM;
            #pragma unroll
            for (int nt = 0; nt < 8; nt++) {
                const int cg = colBase + wn * 64 + nt * 8 + 2 * qc;
                if (tok0 >= 0) {
                    atomicAdd(d0 + cg,     w0 * acc[mt][nt][0]);
                    atomicAdd(d0 + cg + 1, w0 * acc[mt][nt][1]);
                }
                if (tok1 >= 0) {
                    atomicAdd(d1 + cg,     w1 * acc[mt][nt][2]);
                    atomicAdd(d1 + cg + 1, w1 * acc[mt][nt][3]);
                }
            }
        }
    }
}

// ---------------------------------------------------------------------------
extern "C" void kernel_launch(void* const* d_in, const int* in_sizes, int n_in,
                              void* d_out, int out_size) {
    const float* x   = (const float*)d_in[0];   // [8192, 1024]
    const float* gw  = (const float*)d_in[1];   // [8, 1024]
    const float* wfc = (const float*)d_in[2];   // [8, 4096, 1024]
    const float* wpj = (const float*)d_in[3];   // [8, 1024, 4096]
    float* out = (float*)d_out;

    const int SMEM_BYTES = NSTAGE * STAGE_BYTES;   // 196608
    cudaFuncSetAttribute(k_mma<DIM, 0>,  cudaFuncAttributeMaxDynamicSharedMemorySize, SMEM_BYTES);
    cudaFuncSetAttribute(k_mma<HDIM, 1>, cudaFuncAttributeMaxDynamicSharedMemorySize, SMEM_BYTES);

    // fp32 -> fp16 weight conversions
    __half *xh, *wfh, *wph;
    cudaGetSymbolAddress((void**)&xh,  g_xh);
    cudaGetSymbolAddress((void**)&wfh, g_wfch);
    cudaGetSymbolAddress((void**)&wph, g_wpjh);
    {
        int n4 = NEXP * HDIM * DIM / 4;
        k_half<<<(n4 + 255) / 256, 256>>>((const float4*)wfc, (uint2*)wfh, n4);
        k_half<<<(n4 + 255) / 256, 256>>>((const float4*)wpj, (uint2*)wph, n4);
    }

    k_init<<<CAP / 256, 256>>>();
    k_gate<<<N_TOK / 8, 256>>>(x, gw);      // also writes g_xh
    k_scan<<<1, 32>>>(out, out_size);
    k_scatter<<<NSLOT / 256, 256>>>();
    k_zero<<<(N_TOK * (DIM / 4) + 255) / 256, 256>>>((float4*)out);

    dim3 g1(HDIM / BN, MAXTILES);               // 16 x 136
    k_mma<DIM, 0><<<g1, NTHR, SMEM_BYTES>>>(xh, wfh, nullptr);

    dim3 g2(DIM / BN, MAXTILES);                // 4 x 136
    k_mma<HDIM, 1><<<g2, NTHR, SMEM_BYTES>>>(nullptr, wph, out);
}

// round 16
// speedup vs baseline: 1.5170x; 1.5170x over previous
#include <cuda_runtime.h>
#include <cuda_fp16.h>
#include <cstdint>
#include <math.h>

#define N_TOK 8192
#define DIM   1024
#define HDIM  4096
#define NEXP  8
#define NSLOT 16384
#define CAP   17408            // 16384 + 8*128 pad (per-expert pad to 128)
#define MAXTILES 136           // CAP / 128
#define BN    256              // CTA cols
#define KSTG  64               // K halves per stage (128B rows)
#define STAGE_BYTES ((128 + BN) * 128)   // A 16KB + B 32KB = 49152
#define NSTAGE 4
#define NTHR  512
#define NB1   (16 * MAXTILES)  // 2176 GEMM1 tiles
#define NB2   (4 * MAXTILES)   // 544  GEMM2 tiles

// ---------------- scratch (static __device__: no runtime alloc) ------------
__device__ __half g_Hh [(size_t)CAP   * HDIM];       // 142 MB relu^2 out, fp16
__device__ float  g_ys [(size_t)NSLOT * DIM];        // 64 MB per-slot weighted out
__device__ __half g_xh  [(size_t)N_TOK * DIM];       // 16 MB  x in fp16
__device__ __half g_wfch[(size_t)NEXP * HDIM * DIM]; // 64 MB w_fc fp16
__device__ __half g_wpjh[(size_t)NEXP * HDIM * DIM]; // 64 MB w_proj fp16
__device__ int   g_rowTok[CAP];
__device__ int   g_rowSlot[CAP];
__device__ float g_rowW[CAP];
__device__ int   g_slotE[NSLOT];
__device__ float g_slotW[NSLOT];
__device__ int   g_cnt[NEXP];
__device__ int   g_cursor[NEXP];
__device__ int   g_padOff[NEXP + 1];
__device__ int   g_tileE[MAXTILES];
__device__ float g_probSum[NEXP];
__device__ int   g_rowDone[MAXTILES];

// ---------------- helpers ---------------------------------------------------
__device__ __forceinline__ uint32_t smem_to_u32(const void* p) {
    uint32_t a;
    asm("{ .reg .u64 t; cvta.to.shared.u64 t, %1; cvt.u32.u64 %0, t; }"
        : "=r"(a) : "l"(p));
    return a;
}
__device__ __forceinline__ void cpasync16(uint32_t s, const void* g) {
    asm volatile("cp.async.cg.shared.global [%0], [%1], 16;" :: "r"(s), "l"(g) : "memory");
}
__device__ __forceinline__ void ldsm4(uint32_t& r0, uint32_t& r1, uint32_t& r2,
                                      uint32_t& r3, uint32_t addr) {
    asm volatile("ldmatrix.sync.aligned.m8n8.x4.shared.b16 {%0,%1,%2,%3}, [%4];"
                 : "=r"(r0), "=r"(r1), "=r"(r2), "=r"(r3) : "r"(addr));
}
__device__ __forceinline__ void mma_f16(float* c, const uint32_t* a, const uint32_t* b) {
    asm volatile(
        "mma.sync.aligned.m16n8k16.row.col.f32.f16.f16.f32 "
        "{%0,%1,%2,%3}, {%4,%5,%6,%7}, {%8,%9}, {%0,%1,%2,%3};"
        : "+f"(c[0]), "+f"(c[1]), "+f"(c[2]), "+f"(c[3])
        : "r"(a[0]), "r"(a[1]), "r"(a[2]), "r"(a[3]), "r"(b[0]), "r"(b[1]));
}

// ---------------- K_half: fp32 -> fp16 bulk convert (weights) ---------------
__global__ void k_half(const float4* __restrict__ in, uint2* __restrict__ out, int n4) {
    int i = blockIdx.x * blockDim.x + threadIdx.x;
    if (i >= n4) return;
    float4 v = in[i];
    __half2 h0 = __floats2half2_rn(v.x, v.y);
    __half2 h1 = __floats2half2_rn(v.z, v.w);
    out[i] = make_uint2(*(uint32_t*)&h0, *(uint32_t*)&h1);
}

// ---------------- K0: reset -------------------------------------------------
__global__ void k_init() {
    int i = blockIdx.x * blockDim.x + threadIdx.x;
    if (i < CAP) g_rowTok[i] = -1;
    if (i < MAXTILES) g_rowDone[i] = 0;
    if (i < NEXP) { g_cnt[i] = 0; g_cursor[i] = 0; g_probSum[i] = 0.f; }
}

// ---------------- K1: gating (exact fp32, smem gw) + x -> fp16 --------------
__global__ __launch_bounds__(256) void k_gate(const float* __restrict__ x,
                                              const float* __restrict__ gw) {
    __shared__ float sgw[NEXP * DIM];
    __shared__ float sProb[NEXP];
    __shared__ int   sCnt[NEXP];
    int tid = threadIdx.x;
    if (tid < NEXP) { sProb[tid] = 0.f; sCnt[tid] = 0; }
    #pragma unroll
    for (int i = tid; i < NEXP * DIM / 4; i += 256)
        ((float4*)sgw)[i] = ((const float4*)gw)[i];
    __syncthreads();

    int warp = tid >> 5, lane = tid & 31;
    int n = blockIdx.x * 8 + warp;
    const float* xr = x + (size_t)n * DIM;
    float xv[32];
    #pragma unroll
    for (int j = 0; j < 32; j++) xv[j] = xr[j * 32 + lane];

    // fused fp16 conversion of x
    __half* xo = g_xh + (size_t)n * DIM;
    #pragma unroll
    for (int j = 0; j < 32; j++) xo[j * 32 + lane] = __float2half_rn(xv[j]);

    float logit[NEXP];
    #pragma unroll
    for (int e = 0; e < NEXP; e++) {
        const float* g = sgw + e * DIM;
        float s = 0.f;
        #pragma unroll
        for (int j = 0; j < 32; j++) s += xv[j] * g[j * 32 + lane];
        #pragma unroll
        for (int o = 16; o; o >>= 1) s += __shfl_xor_sync(0xffffffffu, s, o);
        logit[e] = s;
    }
    if (lane == 0) {
        float m = logit[0];
        #pragma unroll
        for (int e = 1; e < NEXP; e++) m = fmaxf(m, logit[e]);
        float p[NEXP]; float Z = 0.f;
        #pragma unroll
        for (int e = 0; e < NEXP; e++) { p[e] = expf(logit[e] - m); Z += p[e]; }
        float inv = 1.f / Z;
        #pragma unroll
        for (int e = 0; e < NEXP; e++) p[e] *= inv;
        int i1 = 0;
        #pragma unroll
        for (int e = 1; e < NEXP; e++) if (p[e] > p[i1]) i1 = e;
        int i2 = (i1 == 0) ? 1 : 0;
        #pragma unroll
        for (int e = 0; e < NEXP; e++) if (e != i1 && p[e] > p[i2]) i2 = e;
        float s2 = p[i1] + p[i2];
        g_slotE[2 * n]     = i1;  g_slotW[2 * n]     = p[i1] / s2;
        g_slotE[2 * n + 1] = i2;  g_slotW[2 * n + 1] = p[i2] / s2;
        atomicAdd(&sCnt[i1], 1);
        atomicAdd(&sCnt[i2], 1);
        #pragma unroll
        for (int e = 0; e < NEXP; e++) atomicAdd(&sProb[e], p[e]);
    }
    __syncthreads();
    if (tid < NEXP) {
        atomicAdd(&g_probSum[tid], sProb[tid]);
        atomicAdd(&g_cnt[tid], sCnt[tid]);
    }
}

// ---------------- K2: scan + tile map + balance loss ------------------------
__global__ void k_scan(float* out, int out_size) {
    if (threadIdx.x != 0 || blockIdx.x != 0) return;
    int off = 0;
    for (int e = 0; e < NEXP; e++) {
        g_padOff[e] = off;
        off += ((g_cnt[e] + 127) >> 7) << 7;
    }
    g_padOff[NEXP] = off;
    for (int e = 0; e < NEXP; e++)
        for (int t = g_padOff[e] >> 7; t < (g_padOff[e + 1] >> 7); t++) g_tileE[t] = e;
    for (int t = off >> 7; t < MAXTILES; t++) g_tileE[t] = -1;
    if (out_size > N_TOK * DIM) {
        float l = 0.f;
        for (int e = 0; e < NEXP; e++) l += g_probSum[e] * (float)g_cnt[e];
        out[(size_t)N_TOK * DIM] = l * (float)NEXP / ((float)N_TOK * (float)N_TOK);
    }
}

// ---------------- K3: scatter -----------------------------------------------
__global__ void k_scatter() {
    int s = blockIdx.x * blockDim.x + threadIdx.x;
    if (s >= NSLOT) return;
    int e = g_slotE[s];
    int pos = g_padOff[e] + atomicAdd(&g_cursor[e], 1);
    g_rowTok[pos]  = s >> 1;
    g_rowSlot[pos] = s;
    g_rowW[pos]    = g_slotW[s];
}

// ---------------------------------------------------------------------------
// Fused MoE GEMM pass: one launch, 2720 blocks.
//   bid <  NB1: GEMM1 tile (x=bid&15, y=bid>>4), A = x gathered, W = w_fc[e],
//               epi relu^2 -> g_Hh; then fence + rowDone[y]++.
//   bid >= NB1: GEMM2 tile (x=b2&3, y=b2>>2), spin until rowDone[y]==16,
//               A = g_Hh rows, W = w_proj[e], epi *rowW -> g_ys.
// Mainloop identical to R13 (fastest measured): CTA 128x256, 512 thr,
// 4x4 warps of 32x64, K-stage 64 halves, 4-stage cp.async, XOR swizzle.
// ---------------------------------------------------------------------------
__global__ void __launch_bounds__(NTHR, 1) k_moe(const __half* __restrict__ xh,
                                                 const __half* __restrict__ wfc,
                                                 const __half* __restrict__ wpj) {
    const int bid = blockIdx.x;
    int mode, bx, by, KD;
    const __half* Wg;
    if (bid < NB1) { mode = 0; bx = bid & 15;  by = bid >> 4; KD = DIM;  Wg = wfc; }
    else { int b2 = bid - NB1; mode = 1; bx = b2 & 3; by = b2 >> 2; KD = HDIM; Wg = wpj; }

    const int e = g_tileE[by];
    if (e < 0) return;

    extern __shared__ char smem[];   // NSTAGE * STAGE_BYTES
    const int tid = threadIdx.x;
    const int rowBase = by << 7;
    const int colBase = bx * BN;

    if (mode == 1) {                 // wait for the 16 producer tiles of row by
        if (tid == 0) while (atomicAdd(&g_rowDone[by], 0) < 16) { }
        __syncthreads();             // cp.async.cg reads bypass L1; L2 coherent
    }

    // ---- loader mapping:
    //   A: thread t -> row t>>2, chunks (t&3)*2 .. +1   (2 x cp.async)
    //   B: thread t -> row t>>1, chunks (t&1)*4 .. +3   (4 x cp.async)
    const __half* aSrc;
    {
        int ar = rowBase + (tid >> 2);
        if (mode == 0) {
            int tok = g_rowTok[ar];
            if (tok < 0) tok = 0;                   // pad rows: valid dummy data
            aSrc = xh + (size_t)tok * DIM;
        } else {
            aSrc = g_Hh + (size_t)ar * HDIM;
        }
    }
    const __half* bSrc = Wg + (size_t)e * ((size_t)HDIM * DIM)
                       + (size_t)(colBase + (tid >> 1)) * KD;

    const uint32_t sb = smem_to_u32(smem);
    const int acb = (tid & 3) * 2;                  // A chunk base
    const int bcb = (tid & 1) * 4;                  // B chunk base
    uint32_t aOff[2], bOff[4];
    #pragma unroll
    for (int j = 0; j < 2; j++)
        aOff[j] = (tid >> 2) * 128 + (((acb + j) ^ ((tid >> 2) & 7)) << 4);
    #pragma unroll
    for (int j = 0; j < 4; j++)
        bOff[j] = 16384 + (tid >> 1) * 128 + (((bcb + j) ^ ((tid >> 1) & 7)) << 4);

    const int T = KD / KSTG;

    // prologue: stages 0..NSTAGE-2
    #pragma unroll
    for (int t = 0; t < NSTAGE - 1; t++) {
        uint32_t so = sb + t * STAGE_BYTES;
        const __half* ga = aSrc + t * KSTG;
        const __half* gb = bSrc + t * KSTG;
        #pragma unroll
        for (int j = 0; j < 2; j++) cpasync16(so + aOff[j], ga + (acb + j) * 8);
        #pragma unroll
        for (int j = 0; j < 4; j++) cpasync16(so + bOff[j], gb + (bcb + j) * 8);
        asm volatile("cp.async.commit_group;" ::: "memory");
    }

    // ---- compute mapping (ldmatrix lane geometry)
    const int wid = tid >> 5, lane = tid & 31;
    const int wm = wid >> 2, wn = wid & 3;          // 4x4 warps of 32x64
    const int mat = lane >> 3;
    const int l8  = ((mat & 1) << 3) + (lane & 7);  // row-within-16
    const int cm  = mat >> 1;                       // 16B chunk sub-index
    const int rsw = l8 & 7;                         // reader swizzle
    uint32_t pc[4];
    #pragma unroll
    for (int kb = 0; kb < 4; kb++) pc[kb] = (uint32_t)(((2 * kb + cm) ^ rsw) << 4);
    const uint32_t aLane = (uint32_t)(wm * 4096 + l8 * 128);
    const uint32_t bLane = (uint32_t)(16384 + wn * 8192 + l8 * 128);

    float acc[2][8][4];
    #pragma unroll
    for (int i = 0; i < 2; i++)
        #pragma unroll
        for (int j = 0; j < 8; j++)
            #pragma unroll
            for (int q = 0; q < 4; q++) acc[i][j][q] = 0.f;

    for (int jt = 0; jt < T; jt++) {
        if (jt < T - 2)       asm volatile("cp.async.wait_group 2;" ::: "memory");
        else if (jt == T - 2) asm volatile("cp.async.wait_group 1;" ::: "memory");
        else                  asm volatile("cp.async.wait_group 0;" ::: "memory");
        __syncthreads();

        if (jt + NSTAGE - 1 < T) {
            int t = jt + NSTAGE - 1;
            uint32_t so = sb + (t & (NSTAGE - 1)) * STAGE_BYTES;
            const __half* ga = aSrc + t * KSTG;
            const __half* gb = bSrc + t * KSTG;
            #pragma unroll
            for (int j = 0; j < 2; j++) cpasync16(so + aOff[j], ga + (acb + j) * 8);
            #pragma unroll
            for (int j = 0; j < 4; j++) cpasync16(so + bOff[j], gb + (bcb + j) * 8);
            asm volatile("cp.async.commit_group;" ::: "memory");
        }

        const uint32_t so = sb + (jt & (NSTAGE - 1)) * STAGE_BYTES;
        const uint32_t sA = so + aLane;
        const uint32_t sB = so + bLane;

        #pragma unroll
        for (int kb = 0; kb < 4; kb++) {
            const uint32_t c = pc[kb];
            uint32_t a[2][4], b[8][2];
            #pragma unroll
            for (int mt = 0; mt < 2; mt++)
                ldsm4(a[mt][0], a[mt][1], a[mt][2], a[mt][3], sA + mt * 2048 + c);
            #pragma unroll
            for (int p = 0; p < 4; p++) {
                uint32_t r0, r1, r2, r3;
                ldsm4(r0, r1, r2, r3, sB + p * 2048 + c);
                b[2 * p][0]     = r0;
                b[2 * p + 1][0] = r1;
                b[2 * p][1]     = r2;
                b[2 * p + 1][1] = r3;
            }
            #pragma unroll
            for (int mt = 0; mt < 2; mt++)
                #pragma unroll
                for (int nt = 0; nt < 8; nt++)
                    mma_f16(acc[mt][nt], a[mt], b[nt]);
        }
    }

    // ---- epilogue. Frag: c0,c1 -> row qr cols 2qc,2qc+1; c2,c3 -> row qr+8
    const int qr = lane >> 2, qc = lane & 3;
    #pragma unroll
    for (int mt = 0; mt < 2; mt++) {
        const int r0 = rowBase + wm * 32 + mt * 16 + qr;
        const int r1 = r0 + 8;
        if (mode == 0) {
            #pragma unroll
            for (int nt = 0; nt < 8; nt++) {
                const int cg = colBase + wn * 64 + nt * 8 + 2 * qc;
                float t0 = fmaxf(acc[mt][nt][0], 0.f);
                float t1 = fmaxf(acc[mt][nt][1], 0.f);
                float t2 = fmaxf(acc[mt][nt][2], 0.f);
                float t3 = fmaxf(acc[mt][nt][3], 0.f);
                *(__half2*)(g_Hh + (size_t)r0 * HDIM + cg) = __floats2half2_rn(t0 * t0, t1 * t1);
                *(__half2*)(g_Hh + (size_t)r1 * HDIM + cg) = __floats2half2_rn(t2 * t2, t3 * t3);
            }
        } else {
            int   tok0 = g_rowTok[r0],  tok1 = g_rowTok[r1];
            float w0   = g_rowW[r0],    w1   = g_rowW[r1];
            int   sl0  = g_rowSlot[r0], sl1  = g_rowSlot[r1];
            #pragma unroll
            for (int nt = 0; nt < 8; nt++) {
                const int cg = colBase + wn * 64 + nt * 8 + 2 * qc;
                if (tok0 >= 0)
                    *(float2*)(g_ys + (size_t)sl0 * DIM + cg) =
                        make_float2(w0 * acc[mt][nt][0], w0 * acc[mt][nt][1]);
                if (tok1 >= 0)
                    *(float2*)(g_ys + (size_t)sl1 * DIM + cg) =
                        make_float2(w1 * acc[mt][nt][2], w1 * acc[mt][nt][3]);
            }
        }
    }

    // ---- GEMM1 completion signal (release: stores -> fence -> sync -> atomic)
    if (mode == 0) {
        __threadfence();
        __syncthreads();
        if (tid == 0) atomicAdd(&g_rowDone[by], 1);
    }
}

// ---------------- K6: combine two slots per token ---------------------------
__global__ void k_combine(float* __restrict__ out) {
    int i = blockIdx.x * blockDim.x + threadIdx.x;
    const int PR = DIM / 4;
    if (i >= N_TOK * PR) return;
    int n = i / PR;
    int c = i - n * PR;
    const float4* ys = (const float4*)g_ys;
    float4 a = ys[(size_t)(2 * n) * PR + c];
    float4 b = ys[(size_t)(2 * n + 1) * PR + c];
    float4 o;
    o.x = a.x + b.x; o.y = a.y + b.y; o.z = a.z + b.z; o.w = a.w + b.w;
    ((float4*)out)[(size_t)n * PR + c] = o;
}

// ---------------------------------------------------------------------------
extern "C" void kernel_launch(void* const* d_in, const int* in_sizes, int n_in,
                              void* d_out, int out_size) {
    const float* x   = (const float*)d_in[0];   // [8192, 1024]
    const float* gw  = (const float*)d_in[1];   // [8, 1024]
    const float* wfc = (const float*)d_in[2];   // [8, 4096, 1024]
    const float* wpj = (const float*)d_in[3];   // [8, 1024, 4096]
    float* out = (float*)d_out;

    const int SMEM_BYTES = NSTAGE * STAGE_BYTES;   // 196608
    cudaFuncSetAttribute(k_moe, cudaFuncAttributeMaxDynamicSharedMemorySize, SMEM_BYTES);

    // fp32 -> fp16 weight conversions
    __half *xh, *wfh, *wph;
    cudaGetSymbolAddress((void**)&xh,  g_xh);
    cudaGetSymbolAddress((void**)&wfh, g_wfch);
    cudaGetSymbolAddress((void**)&wph, g_wpjh);
    {
        int n4 = NEXP * HDIM * DIM / 4;
        k_half<<<(n4 + 255) / 256, 256>>>((const float4*)wfc, (uint2*)wfh, n4);
        k_half<<<(n4 + 255) / 256, 256>>>((const float4*)wpj, (uint2*)wph, n4);
    }

    k_init<<<CAP / 256, 256>>>();
    k_gate<<<N_TOK / 8, 256>>>(x, gw);      // also writes g_xh
    k_scan<<<1, 32>>>(out, out_size);
    k_scatter<<<NSLOT / 256, 256>>>();

    k_moe<<<NB1 + NB2, NTHR, SMEM_BYTES>>>(xh, wfh, wph);

    k_combine<<<(N_TOK * (DIM / 4) + 255) / 256, 256>>>(out);
}

// round 17
// speedup vs baseline: 1.5367x; 1.0129x over previous
#include <cuda_runtime.h>
#include <cuda_fp16.h>
#include <cstdint>
#include <math.h>

#define N_TOK 8192
#define DIM   1024
#define HDIM  4096
#define NEXP  8
#define NSLOT 16384
#define CAP   17408            // 16384 + 8*128 pad (per-expert pad to 128)
#define MAXTILES 136           // CAP / 128
#define BN    256              // CTA cols
#define KSTG  64               // K halves per stage (128B rows)
#define STAGE_BYTES ((128 + BN) * 128)   // A 16KB + B 32KB = 49152
#define NSTAGE 4
#define NTHR  512
#define NB1   (16 * MAXTILES)  // 2176 GEMM1 tiles
#define NB2   (4 * MAXTILES)   // 544  GEMM2 tiles
#define NCV   512              // converter blocks (wpj inside k_moe, wfc inside k_gate)
#define N4W   (NEXP * HDIM * DIM / 4)   // float4 count per weight tensor

// ---------------- scratch (static __device__: no runtime alloc) ------------
__device__ __half g_Hh [(size_t)CAP   * HDIM];       // 142 MB relu^2 out, fp16
__device__ float  g_ys [(size_t)NSLOT * DIM];        // 64 MB per-slot weighted out
__device__ __half g_xh  [(size_t)N_TOK * DIM];       // 16 MB  x in fp16
__device__ __half g_wfch[(size_t)NEXP * HDIM * DIM]; // 64 MB w_fc fp16
__device__ __half g_wpjh[(size_t)NEXP * HDIM * DIM]; // 64 MB w_proj fp16
__device__ int   g_rowTok[CAP];
__device__ int   g_rowSlot[CAP];
__device__ float g_rowW[CAP];
__device__ int   g_slotE[NSLOT];
__device__ float g_slotW[NSLOT];
__device__ int   g_cnt[NEXP];
__device__ int   g_cursor[NEXP];
__device__ int   g_padOff[NEXP + 1];
__device__ int   g_tileE[MAXTILES];
__device__ float g_probSum[NEXP];
__device__ int   g_rowDone[MAXTILES];
__device__ int   g_wpjDone;

// ---------------- helpers ---------------------------------------------------
__device__ __forceinline__ uint32_t smem_to_u32(const void* p) {
    uint32_t a;
    asm("{ .reg .u64 t; cvta.to.shared.u64 t, %1; cvt.u32.u64 %0, t; }"
        : "=r"(a) : "l"(p));
    return a;
}
__device__ __forceinline__ void cpasync16(uint32_t s, const void* g) {
    asm volatile("cp.async.cg.shared.global [%0], [%1], 16;" :: "r"(s), "l"(g) : "memory");
}
__device__ __forceinline__ void ldsm4(uint32_t& r0, uint32_t& r1, uint32_t& r2,
                                      uint32_t& r3, uint32_t addr) {
    asm volatile("ldmatrix.sync.aligned.m8n8.x4.shared.b16 {%0,%1,%2,%3}, [%4];"
                 : "=r"(r0), "=r"(r1), "=r"(r2), "=r"(r3) : "r"(addr));
}
__device__ __forceinline__ void mma_f16(float* c, const uint32_t* a, const uint32_t* b) {
    asm volatile(
        "mma.sync.aligned.m16n8k16.row.col.f32.f16.f16.f32 "
        "{%0,%1,%2,%3}, {%4,%5,%6,%7}, {%8,%9}, {%0,%1,%2,%3};"
        : "+f"(c[0]), "+f"(c[1]), "+f"(c[2]), "+f"(c[3])
        : "r"(a[0]), "r"(a[1]), "r"(a[2]), "r"(a[3]), "r"(b[0]), "r"(b[1]));
}
__device__ __forceinline__ void cvt_slice(const float4* __restrict__ in,
                                          uint2* __restrict__ out,
                                          int start, int stride) {
    for (int i = start; i < N4W; i += stride) {
        float4 v = in[i];
        __half2 h0 = __floats2half2_rn(v.x, v.y);
        __half2 h1 = __floats2half2_rn(v.z, v.w);
        out[i] = make_uint2(*(uint32_t*)&h0, *(uint32_t*)&h1);
    }
}

// ---------------- K0: reset -------------------------------------------------
__global__ void k_init() {
    int i = blockIdx.x * blockDim.x + threadIdx.x;
    if (i < CAP) g_rowTok[i] = -1;
    if (i < MAXTILES) g_rowDone[i] = 0;
    if (i == 0) g_wpjDone = 0;
    if (i < NEXP) { g_cnt[i] = 0; g_cursor[i] = 0; g_probSum[i] = 0.f; }
}

// ---------------- K1: gating (exact fp32, smem gw) + x->fp16 + wfc->fp16 ----
__global__ __launch_bounds__(256) void k_gate(const float* __restrict__ x,
                                              const float* __restrict__ gw,
                                              const float4* __restrict__ wfc) {
    // trailing blocks: convert w_fc to fp16 (overlaps with gating blocks)
    if (blockIdx.x >= N_TOK / 8) {
        int cid = blockIdx.x - N_TOK / 8;
        cvt_slice(wfc, (uint2*)g_wfch, cid * 256 + threadIdx.x, NCV * 256);
        return;
    }

    __shared__ float sgw[NEXP * DIM];
    __shared__ float sProb[NEXP];
    __shared__ int   sCnt[NEXP];
    int tid = threadIdx.x;
    if (tid < NEXP) { sProb[tid] = 0.f; sCnt[tid] = 0; }
    #pragma unroll
    for (int i = tid; i < NEXP * DIM / 4; i += 256)
        ((float4*)sgw)[i] = ((const float4*)gw)[i];
    __syncthreads();

    int warp = tid >> 5, lane = tid & 31;
    int n = blockIdx.x * 8 + warp;
    const float* xr = x + (size_t)n * DIM;
    float xv[32];
    #pragma unroll
    for (int j = 0; j < 32; j++) xv[j] = xr[j * 32 + lane];

    // fused fp16 conversion of x
    __half* xo = g_xh + (size_t)n * DIM;
    #pragma unroll
    for (int j = 0; j < 32; j++) xo[j * 32 + lane] = __float2half_rn(xv[j]);

    float logit[NEXP];
    #pragma unroll
    for (int e = 0; e < NEXP; e++) {
        const float* g = sgw + e * DIM;
        float s = 0.f;
        #pragma unroll
        for (int j = 0; j < 32; j++) s += xv[j] * g[j * 32 + lane];
        #pragma unroll
        for (int o = 16; o; o >>= 1) s += __shfl_xor_sync(0xffffffffu, s, o);
        logit[e] = s;
    }
    if (lane == 0) {
        float m = logit[0];
        #pragma unroll
        for (int e = 1; e < NEXP; e++) m = fmaxf(m, logit[e]);
        float p[NEXP]; float Z = 0.f;
        #pragma unroll
        for (int e = 0; e < NEXP; e++) { p[e] = expf(logit[e] - m); Z += p[e]; }
        float inv = 1.f / Z;
        #pragma unroll
        for (int e = 0; e < NEXP; e++) p[e] *= inv;
        int i1 = 0;
        #pragma unroll
        for (int e = 1; e < NEXP; e++) if (p[e] > p[i1]) i1 = e;
        int i2 = (i1 == 0) ? 1 : 0;
        #pragma unroll
        for (int e = 0; e < NEXP; e++) if (e != i1 && p[e] > p[i2]) i2 = e;
        float s2 = p[i1] + p[i2];
        g_slotE[2 * n]     = i1;  g_slotW[2 * n]     = p[i1] / s2;
        g_slotE[2 * n + 1] = i2;  g_slotW[2 * n + 1] = p[i2] / s2;
        atomicAdd(&sCnt[i1], 1);
        atomicAdd(&sCnt[i2], 1);
        #pragma unroll
        for (int e = 0; e < NEXP; e++) atomicAdd(&sProb[e], p[e]);
    }
    __syncthreads();
    if (tid < NEXP) {
        atomicAdd(&g_probSum[tid], sProb[tid]);
        atomicAdd(&g_cnt[tid], sCnt[tid]);
    }
}

// ---------------- K2: scan + tile map + balance loss ------------------------
__global__ void k_scan(float* out, int out_size) {
    if (threadIdx.x != 0 || blockIdx.x != 0) return;
    int off = 0;
    for (int e = 0; e < NEXP; e++) {
        g_padOff[e] = off;
        off += ((g_cnt[e] + 127) >> 7) << 7;
    }
    g_padOff[NEXP] = off;
    for (int e = 0; e < NEXP; e++)
        for (int t = g_padOff[e] >> 7; t < (g_padOff[e + 1] >> 7); t++) g_tileE[t] = e;
    for (int t = off >> 7; t < MAXTILES; t++) g_tileE[t] = -1;
    if (out_size > N_TOK * DIM) {
        float l = 0.f;
        for (int e = 0; e < NEXP; e++) l += g_probSum[e] * (float)g_cnt[e];
        out[(size_t)N_TOK * DIM] = l * (float)NEXP / ((float)N_TOK * (float)N_TOK);
    }
}

// ---------------- K3: scatter -----------------------------------------------
__global__ void k_scatter() {
    int s = blockIdx.x * blockDim.x + threadIdx.x;
    if (s >= NSLOT) return;
    int e = g_slotE[s];
    int pos = g_padOff[e] + atomicAdd(&g_cursor[e], 1);
    g_rowTok[pos]  = s >> 1;
    g_rowSlot[pos] = s;
    g_rowW[pos]    = g_slotW[s];
}

// ---------------------------------------------------------------------------
// Fused MoE GEMM pass: one launch, NB1 + NCV + NB2 blocks.
//   bid <  NB1:           GEMM1 tile -> g_Hh; fence + rowDone[y]++.
//   NB1 <= bid < NB1+NCV: convert wpj slice to fp16; fence + wpjDone++.
//                         (runs under tensor-saturated GEMM1 -> ~free)
//   bid >= NB1+NCV:       GEMM2 tile; spin on wpjDone==NCV & rowDone[y]==16.
// Dispatch is bid-ordered: converters precede all their waiters -> no deadlock.
// Mainloop identical to R13: CTA 128x256, 512 thr, 4x4 warps of 32x64,
// K-stage 64 halves, 4-stage cp.async, XOR swizzle.
// ---------------------------------------------------------------------------
__global__ void __launch_bounds__(NTHR, 1) k_moe(const __half* __restrict__ xh,
                                                 const __half* __restrict__ wfc,
                                                 const __half* __restrict__ wpj,
                                                 const float4* __restrict__ wpj32) {
    const int bid = blockIdx.x;
    int mode, bx, by, KD;
    const __half* Wg;
    if (bid < NB1) { mode = 0; bx = bid & 15; by = bid >> 4; KD = DIM; Wg = wfc; }
    else if (bid < NB1 + NCV) {
        cvt_slice(wpj32, (uint2*)g_wpjh, (bid - NB1) * NTHR + threadIdx.x, NCV * NTHR);
        __threadfence();
        __syncthreads();
        if (threadIdx.x == 0) atomicAdd(&g_wpjDone, 1);
        return;
    } else {
        int b2 = bid - NB1 - NCV;
        mode = 1; bx = b2 & 3; by = b2 >> 2; KD = HDIM; Wg = wpj;
    }

    const int e = g_tileE[by];
    if (e < 0) return;

    extern __shared__ char smem[];   // NSTAGE * STAGE_BYTES
    const int tid = threadIdx.x;
    const int rowBase = by << 7;
    const int colBase = bx * BN;

    if (mode == 1) {                 // wait for wpj fp16 + the 16 producer tiles
        if (tid == 0) {
            while (atomicAdd(&g_wpjDone, 0) < NCV) { }
            while (atomicAdd(&g_rowDone[by], 0) < 16) { }
        }
        __syncthreads();             // cp.async.cg reads bypass L1; L2 coherent
    }

    // ---- loader mapping:
    //   A: thread t -> row t>>2, chunks (t&3)*2 .. +1   (2 x cp.async)
    //   B: thread t -> row t>>1, chunks (t&1)*4 .. +3   (4 x cp.async)
    const __half* aSrc;
    {
        int ar = rowBase + (tid >> 2);
        if (mode == 0) {
            int tok = g_rowTok[ar];
            if (tok < 0) tok = 0;                   // pad rows: valid dummy data
            aSrc = xh + (size_t)tok * DIM;
        } else {
            aSrc = g_Hh + (size_t)ar * HDIM;
        }
    }
    const __half* bSrc = Wg + (size_t)e * ((size_t)HDIM * DIM)
                       + (size_t)(colBase + (tid >> 1)) * KD;

    const uint32_t sb = smem_to_u32(smem);
    const int acb = (tid & 3) * 2;                  // A chunk base
    const int bcb = (tid & 1) * 4;                  // B chunk base
    uint32_t aOff[2], bOff[4];
    #pragma unroll
    for (int j = 0; j < 2; j++)
        aOff[j] = (tid >> 2) * 128 + (((acb + j) ^ ((tid >> 2) & 7)) << 4);
    #pragma unroll
    for (int j = 0; j < 4; j++)
        bOff[j] = 16384 + (tid >> 1) * 128 + (((bcb + j) ^ ((tid >> 1) & 7)) << 4);

    const int T = KD / KSTG;

    // prologue: stages 0..NSTAGE-2
    #pragma unroll
    for (int t = 0; t < NSTAGE - 1; t++) {
        uint32_t so = sb + t * STAGE_BYTES;
        const __half* ga = aSrc + t * KSTG;
        const __half* gb = bSrc + t * KSTG;
        #pragma unroll
        for (int j = 0; j < 2; j++) cpasync16(so + aOff[j], ga + (acb + j) * 8);
        #pragma unroll
        for (int j = 0; j < 4; j++) cpasync16(so + bOff[j], gb + (bcb + j) * 8);
        asm volatile("cp.async.commit_group;" ::: "memory");
    }

    // ---- compute mapping (ldmatrix lane geometry)
    const int wid = tid >> 5, lane = tid & 31;
    const int wm = wid >> 2, wn = wid & 3;          // 4x4 warps of 32x64
    const int mat = lane >> 3;
    const int l8  = ((mat & 1) << 3) + (lane & 7);  // row-within-16
    const int cm  = mat >> 1;                       // 16B chunk sub-index
    const int rsw = l8 & 7;                         // reader swizzle
    uint32_t pc[4];
    #pragma unroll
    for (int kb = 0; kb < 4; kb++) pc[kb] = (uint32_t)(((2 * kb + cm) ^ rsw) << 4);
    const uint32_t aLane = (uint32_t)(wm * 4096 + l8 * 128);
    const uint32_t bLane = (uint32_t)(16384 + wn * 8192 + l8 * 128);

    float acc[2][8][4];
    #pragma unroll
    for (int i = 0; i < 2; i++)
        #pragma unroll
        for (int j = 0; j < 8; j++)
            #pragma unroll
            for (int q = 0; q < 4; q++) acc[i][j][q] = 0.f;

    for (int jt = 0; jt < T; jt++) {
        if (jt < T - 2)       asm volatile("cp.async.wait_group 2;" ::: "memory");
        else if (jt == T - 2) asm volatile("cp.async.wait_group 1;" ::: "memory");
        else                  asm volatile("cp.async.wait_group 0;" ::: "memory");
        __syncthreads();

        if (jt + NSTAGE - 1 < T) {
            int t = jt + NSTAGE - 1;
            uint32_t so = sb + (t & (NSTAGE - 1)) * STAGE_BYTES;
            const __half* ga = aSrc + t * KSTG;
            const __half* gb = bSrc + t * KSTG;
            #pragma unroll
            for (int j = 0; j < 2; j++) cpasync16(so + aOff[j], ga + (acb + j) * 8);
            #pragma unroll
            for (int j = 0; j < 4; j++) cpasync16(so + bOff[j], gb + (bcb + j) * 8);
            asm volatile("cp.async.commit_group;" ::: "memory");
        }

        const uint32_t so = sb + (jt & (NSTAGE - 1)) * STAGE_BYTES;
        const uint32_t sA = so + aLane;
        const uint32_t sB = so + bLane;

        #pragma unroll
        for (int kb = 0; kb < 4; kb++) {
            const uint32_t c = pc[kb];
            uint32_t a[2][4], b[8][2];
            #pragma unroll
            for (int mt = 0; mt < 2; mt++)
                ldsm4(a[mt][0], a[mt][1], a[mt][2], a[mt][3], sA + mt * 2048 + c);
            #pragma unroll
            for (int p = 0; p < 4; p++) {
                uint32_t r0, r1, r2, r3;
                ldsm4(r0, r1, r2, r3, sB + p * 2048 + c);
                b[2 * p][0]     = r0;
                b[2 * p + 1][0] = r1;
                b[2 * p][1]     = r2;
                b[2 * p + 1][1] = r3;
            }
            #pragma unroll
            for (int mt = 0; mt < 2; mt++)
                #pragma unroll
                for (int nt = 0; nt < 8; nt++)
                    mma_f16(acc[mt][nt], a[mt], b[nt]);
        }
    }

    // ---- epilogue. Frag: c0,c1 -> row qr cols 2qc,2qc+1; c2,c3 -> row qr+8
    const int qr = lane >> 2, qc = lane & 3;
    #pragma unroll
    for (int mt = 0; mt < 2; mt++) {
        const int r0 = rowBase + wm * 32 + mt * 16 + qr;
        const int r1 = r0 + 8;
        if (mode == 0) {
            #pragma unroll
            for (int nt = 0; nt < 8; nt++) {
                const int cg = colBase + wn * 64 + nt * 8 + 2 * qc;
                float t0 = fmaxf(acc[mt][nt][0], 0.f);
                float t1 = fmaxf(acc[mt][nt][1], 0.f);
                float t2 = fmaxf(acc[mt][nt][2], 0.f);
                float t3 = fmaxf(acc[mt][nt][3], 0.f);
                *(__half2*)(g_Hh + (size_t)r0 * HDIM + cg) = __floats2half2_rn(t0 * t0, t1 * t1);
                *(__half2*)(g_Hh + (size_t)r1 * HDIM + cg) = __floats2half2_rn(t2 * t2, t3 * t3);
            }
        } else {
            int   tok0 = g_rowTok[r0],  tok1 = g_rowTok[r1];
            float w0   = g_rowW[r0],    w1   = g_rowW[r1];
            int   sl0  = g_rowSlot[r0], sl1  = g_rowSlot[r1];
            #pragma unroll
            for (int nt = 0; nt < 8; nt++) {
                const int cg = colBase + wn * 64 + nt * 8 + 2 * qc;
                if (tok0 >= 0)
                    *(float2*)(g_ys + (size_t)sl0 * DIM + cg) =
                        make_float2(w0 * acc[mt][nt][0], w0 * acc[mt][nt][1]);
                if (tok1 >= 0)
                    *(float2*)(g_ys + (size_t)sl1 * DIM + cg) =
                        make_float2(w1 * acc[mt][nt][2], w1 * acc[mt][nt][3]);
            }
        }
    }

    // ---- GEMM1 completion signal (release: stores -> fence -> sync -> atomic)
    if (mode == 0) {
        __threadfence();
        __syncthreads();
        if (tid == 0) atomicAdd(&g_rowDone[by], 1);
    }
}

// ---------------- K6: combine two slots per token ---------------------------
__global__ void k_combine(float* __restrict__ out) {
    int i = blockIdx.x * blockDim.x + threadIdx.x;
    const int PR = DIM / 4;
    if (i >= N_TOK * PR) return;
    int n = i / PR;
    int c = i - n * PR;
    const float4* ys = (const float4*)g_ys;
    float4 a = ys[(size_t)(2 * n) * PR + c];
    float4 b = ys[(size_t)(2 * n + 1) * PR + c];
    float4 o;
    o.x = a.x + b.x; o.y = a.y + b.y; o.z = a.z + b.z; o.w = a.w + b.w;
    ((float4*)out)[(size_t)n * PR + c] = o;
}

// ---------------------------------------------------------------------------
extern "C" void kernel_launch(void* const* d_in, const int* in_sizes, int n_in,
                              void* d_out, int out_size) {
    const float* x   = (const float*)d_in[0];   // [8192, 1024]
    const float* gw  = (const float*)d_in[1];   // [8, 1024]
    const float* wfc = (const float*)d_in[2];   // [8, 4096, 1024]
    const float* wpj = (const float*)d_in[3];   // [8, 1024, 4096]
    float* out = (float*)d_out;

    const int SMEM_BYTES = NSTAGE * STAGE_BYTES;   // 196608
    cudaFuncSetAttribute(k_moe, cudaFuncAttributeMaxDynamicSharedMemorySize, SMEM_BYTES);

    __half *xh, *wfh, *wph;
    cudaGetSymbolAddress((void**)&xh,  g_xh);
    cudaGetSymbolAddress((void**)&wfh, g_wfch);
    cudaGetSymbolAddress((void**)&wph, g_wpjh);

    k_init<<<CAP / 256, 256>>>();
    // gating + x->fp16 + (fused) wfc->fp16
    k_gate<<<N_TOK / 8 + NCV, 256>>>(x, gw, (const float4*)wfc);
    k_scan<<<1, 32>>>(out, out_size);
    k_scatter<<<NSLOT / 256, 256>>>();

    // GEMM1 tiles + (fused) wpj->fp16 converters + GEMM2 tiles
    k_moe<<<NB1 + NCV + NB2, NTHR, SMEM_BYTES>>>(xh, wfh, wph, (const float4*)wpj);

    k_combine<<<(N_TOK * (DIM / 4) + 255) / 256, 256>>>(out);
}